// round 1
// baseline (speedup 1.0000x reference)
#include <cuda_runtime.h>

// Problem constants
namespace {
constexpr int kB = 16;
constexpr int kT = 2048;
constexpr int kC = 1024;
constexpr int kH = 64;
constexpr int kRows = kB * kT;     // 32768
constexpr int kQT = kT / 64;       // 32 q-tiles per batch
constexpr int LD = 68;             // padded smem row stride (floats)
}

// Scratch for Q, K, V projections (allocation-free scratch via __device__ globals)
__device__ float g_Q[kRows * kH];
__device__ float g_K[kRows * kH];
__device__ float g_V[kRows * kH];

// ---------------------------------------------------------------------------
// Kernel 1: fused QKV projection.
// GEMM [32768 x 1024] * [1024 x 192] (+bias), 192 cols = Wq|Wk|Wv.
// Block: 64 rows x 192 cols, 256 threads (16x16), 4x12 per-thread tile.
// ---------------------------------------------------------------------------
__global__ __launch_bounds__(256, 2)
void qkv_kernel(const float* __restrict__ x,
                const float* __restrict__ Wq, const float* __restrict__ bq,
                const float* __restrict__ Wk, const float* __restrict__ bk,
                const float* __restrict__ Wv, const float* __restrict__ bv) {
    __shared__ float xs[64][33];    // 64 rows x 32 k, padded
    __shared__ float ws[32][192];   // 32 k x 192 cols

    const int tid = threadIdx.x;
    const int tx = tid & 15;
    const int ty = tid >> 4;
    const int row0 = blockIdx.x * 64;
    const int col0 = tx * 12;

    float acc[4][12];
#pragma unroll
    for (int c = 0; c < 12; ++c) {
        const int col = col0 + c;
        const float bias = (col < 64) ? bq[col] : (col < 128) ? bk[col - 64] : bv[col - 128];
#pragma unroll
        for (int r = 0; r < 4; ++r) acc[r][c] = bias;
    }

    for (int k0 = 0; k0 < kC; k0 += 32) {
        // Stage x tile (64x32): coalesced, 8 elems/thread
#pragma unroll
        for (int i = 0; i < 8; ++i) {
            const int idx = tid + i * 256;
            const int r = idx >> 5, kk = idx & 31;
            xs[r][kk] = x[(size_t)(row0 + r) * kC + (k0 + kk)];
        }
        // Stage W tile (32x192): 24 elems/thread
#pragma unroll
        for (int i = 0; i < 24; ++i) {
            const int idx = tid + i * 256;
            const int kk = idx / 192, col = idx % 192;
            const float* W = (col < 64) ? Wq : (col < 128) ? Wk : Wv;
            ws[kk][col] = W[(size_t)(k0 + kk) * kH + (col & 63)];
        }
        __syncthreads();

#pragma unroll 4
        for (int kk = 0; kk < 32; ++kk) {
            float xv[4];
#pragma unroll
            for (int r = 0; r < 4; ++r) xv[r] = xs[ty * 4 + r][kk];
            float wv[12];
#pragma unroll
            for (int c = 0; c < 12; ++c) wv[c] = ws[kk][col0 + c];
#pragma unroll
            for (int r = 0; r < 4; ++r)
#pragma unroll
                for (int c = 0; c < 12; ++c)
                    acc[r][c] = fmaf(xv[r], wv[c], acc[r][c]);
        }
        __syncthreads();
    }

#pragma unroll
    for (int r = 0; r < 4; ++r) {
        const int row = row0 + ty * 4 + r;
#pragma unroll
        for (int c = 0; c < 12; ++c) {
            const int col = col0 + c;
            const float v = acc[r][c];
            if (col < 64)       g_Q[row * kH + col] = v;
            else if (col < 128) g_K[row * kH + (col - 64)] = v;
            else                g_V[row * kH + (col - 128)] = v;
        }
    }
}

// ---------------------------------------------------------------------------
// Kernel 2: causal flash attention, fp32.
// One block = one (batch, 64-query tile). BM=BN=64, H=64.
// 256 threads = 16x16; thread owns 4 query rows (ty*4+r).
//  - QK^T phase: thread owns S columns {c*16+tx} (conflict-friendly K reads)
//  - PV phase:   thread owns O head-dims {tx*4..tx*4+3} (float4 V reads)
// P tile is the bridge between the two column mappings.
// ---------------------------------------------------------------------------
__global__ __launch_bounds__(256, 2)
void attn_kernel(float* __restrict__ out) {
    extern __shared__ float sm[];
    float* Qs = sm;
    float* Ks = sm + 64 * LD;
    float* Vs = sm + 2 * 64 * LD;
    float* Ps = sm + 3 * 64 * LD;

    const int tid = threadIdx.x;
    const int tx = tid & 15;
    const int ty = tid >> 4;
    const int b  = blockIdx.x & 15;
    const int qt = (kQT - 1) - (blockIdx.x >> 4);  // heaviest tiles launch first
    const int q0 = qt * 64;

    const float* Qg = g_Q + (size_t)b * kT * kH;
    const float* Kg = g_K + (size_t)b * kT * kH;
    const float* Vg = g_V + (size_t)b * kT * kH;

    // Load Q tile once
#pragma unroll
    for (int i = 0; i < 16; ++i) {
        const int idx = tid + i * 256;
        const int r = idx >> 6, h = idx & 63;
        Qs[r * LD + h] = Qg[(q0 + r) * kH + h];
    }

    float m[4], l[4], o[4][4];
#pragma unroll
    for (int r = 0; r < 4; ++r) {
        m[r] = -1e30f;
        l[r] = 0.f;
#pragma unroll
        for (int c = 0; c < 4; ++c) o[r][c] = 0.f;
    }

    for (int jt = 0; jt <= qt; ++jt) {
        const int j0 = jt * 64;
        __syncthreads();  // protect K/V/P tiles from prior iteration's readers
#pragma unroll
        for (int i = 0; i < 16; ++i) {
            const int idx = tid + i * 256;
            const int r = idx >> 6, h = idx & 63;
            Ks[r * LD + h] = Kg[(j0 + r) * kH + h];
            Vs[r * LD + h] = Vg[(j0 + r) * kH + h];
        }
        __syncthreads();

        // ---- S = Q K^T ----
        float s[4][4];
#pragma unroll
        for (int r = 0; r < 4; ++r)
#pragma unroll
            for (int c = 0; c < 4; ++c) s[r][c] = 0.f;

#pragma unroll 4
        for (int h = 0; h < 64; h += 4) {
            float4 qv[4], kv[4];
#pragma unroll
            for (int r = 0; r < 4; ++r)
                qv[r] = *reinterpret_cast<const float4*>(&Qs[(ty * 4 + r) * LD + h]);
#pragma unroll
            for (int c = 0; c < 4; ++c)
                kv[c] = *reinterpret_cast<const float4*>(&Ks[(c * 16 + tx) * LD + h]);
#pragma unroll
            for (int r = 0; r < 4; ++r)
#pragma unroll
                for (int c = 0; c < 4; ++c) {
                    s[r][c] = fmaf(qv[r].x, kv[c].x, s[r][c]);
                    s[r][c] = fmaf(qv[r].y, kv[c].y, s[r][c]);
                    s[r][c] = fmaf(qv[r].z, kv[c].z, s[r][c]);
                    s[r][c] = fmaf(qv[r].w, kv[c].w, s[r][c]);
                }
        }

        // ---- scale + causal mask + online softmax ----
        const float scale = 0.125f;  // 1/sqrt(64)
        float rowmax[4];
#pragma unroll
        for (int r = 0; r < 4; ++r) {
            const int qg = q0 + ty * 4 + r;
            float rm = -1e30f;
#pragma unroll
            for (int c = 0; c < 4; ++c) {
                const int kg = j0 + c * 16 + tx;
                const float v = (kg <= qg) ? s[r][c] * scale : -1e30f;
                s[r][c] = v;
                rm = fmaxf(rm, v);
            }
            rowmax[r] = rm;
        }
        // reduce across the 16 lanes that share each row (lane = (ty&1)*16 + tx)
#pragma unroll
        for (int off = 1; off < 16; off <<= 1)
#pragma unroll
            for (int r = 0; r < 4; ++r)
                rowmax[r] = fmaxf(rowmax[r], __shfl_xor_sync(0xffffffffu, rowmax[r], off));

        float alpha[4], rowsum[4];
#pragma unroll
        for (int r = 0; r < 4; ++r) {
            const float mn = fmaxf(m[r], rowmax[r]);
            alpha[r] = __expf(m[r] - mn);
            m[r] = mn;
            float rs = 0.f;
#pragma unroll
            for (int c = 0; c < 4; ++c) {
                const float p = __expf(s[r][c] - mn);
                Ps[(ty * 4 + r) * LD + (c * 16 + tx)] = p;  // conflict-free scatter
                rs += p;
            }
            rowsum[r] = rs;
        }
#pragma unroll
        for (int off = 1; off < 16; off <<= 1)
#pragma unroll
            for (int r = 0; r < 4; ++r)
                rowsum[r] += __shfl_xor_sync(0xffffffffu, rowsum[r], off);
#pragma unroll
        for (int r = 0; r < 4; ++r) {
            l[r] = l[r] * alpha[r] + rowsum[r];
#pragma unroll
            for (int c = 0; c < 4; ++c) o[r][c] *= alpha[r];
        }
        __syncthreads();  // P tile fully written before PV reads

        // ---- O += P @ V ----
#pragma unroll 4
        for (int j = 0; j < 64; j += 4) {
            float vvf[4][4];
#pragma unroll
            for (int jj = 0; jj < 4; ++jj) {
                const float4 vv = *reinterpret_cast<const float4*>(&Vs[(j + jj) * LD + tx * 4]);
                vvf[jj][0] = vv.x; vvf[jj][1] = vv.y; vvf[jj][2] = vv.z; vvf[jj][3] = vv.w;
            }
#pragma unroll
            for (int r = 0; r < 4; ++r) {
                // broadcast float4 read of this thread's P row
                const float4 p = *reinterpret_cast<const float4*>(&Ps[(ty * 4 + r) * LD + j]);
                const float pr[4] = {p.x, p.y, p.z, p.w};
#pragma unroll
                for (int jj = 0; jj < 4; ++jj) {
                    o[r][0] = fmaf(pr[jj], vvf[jj][0], o[r][0]);
                    o[r][1] = fmaf(pr[jj], vvf[jj][1], o[r][1]);
                    o[r][2] = fmaf(pr[jj], vvf[jj][2], o[r][2]);
                    o[r][3] = fmaf(pr[jj], vvf[jj][3], o[r][3]);
                }
            }
        }
    }

    // ---- epilogue: normalize + store ----
#pragma unroll
    for (int r = 0; r < 4; ++r) {
        const float inv = 1.0f / l[r];
        const size_t row = (size_t)b * kT + q0 + ty * 4 + r;
        float4 res;
        res.x = o[r][0] * inv;
        res.y = o[r][1] * inv;
        res.z = o[r][2] * inv;
        res.w = o[r][3] * inv;
        *reinterpret_cast<float4*>(&out[row * kH + tx * 4]) = res;
    }
}

// ---------------------------------------------------------------------------
extern "C" void kernel_launch(void* const* d_in, const int* in_sizes, int n_in,
                              void* d_out, int out_size) {
    (void)in_sizes; (void)n_in; (void)out_size;
    const float* x  = (const float*)d_in[0];
    const float* Wq = (const float*)d_in[1];
    const float* bq = (const float*)d_in[2];
    const float* Wk = (const float*)d_in[3];
    const float* bk = (const float*)d_in[4];
    const float* Wv = (const float*)d_in[5];
    const float* bv = (const float*)d_in[6];
    float* out = (float*)d_out;

    // Fused QKV projection
    qkv_kernel<<<kRows / 64, 256>>>(x, Wq, bq, Wk, bk, Wv, bv);

    // Flash attention (69.6 KB dynamic smem -> needs opt-in attribute; idempotent)
    constexpr int kSmemBytes = 4 * 64 * LD * (int)sizeof(float);
    cudaFuncSetAttribute(attn_kernel, cudaFuncAttributeMaxDynamicSharedMemorySize,
                         kSmemBytes);
    attn_kernel<<<kB * kQT, 256, kSmemBytes>>>(out);
}

// round 3
// speedup vs baseline: 1.7233x; 1.7233x over previous
#include <cuda_runtime.h>
#include <cuda_bf16.h>
#include <cstdint>

// ---------------------------------------------------------------------------
// Problem constants
// ---------------------------------------------------------------------------
namespace {
constexpr int kB = 16;
constexpr int kT = 2048;
constexpr int kC = 1024;
constexpr int kH = 64;
constexpr int kRows = kB * kT;     // 32768
constexpr int kQT = kT / 64;       // 32 q-tiles per batch
constexpr int LD = 68;             // padded smem row stride (floats) for attn

// QKV GEMM smem layout (bytes). Rows padded to 80B (20 words) -> LDS
// bank pattern (20r+c) mod 32 is conflict-free for r in 0..7, c in 0..3.
constexpr int OFF_AHI = 0;          // 128 rows * 80B
constexpr int OFF_ALO = 10240;
constexpr int OFF_BHI = 20480;      // 192 rows * 80B
constexpr int OFF_BLO = 35840;
constexpr int BUFB    = 51200;      // one pipeline buffer
constexpr int QKV_SMEM = 2 * BUFB;  // 102400
}

// Scratch (__device__ globals: allocation-free)
__device__ float g_Q[kRows * kH];
__device__ float g_K[kRows * kH];
__device__ float g_V[kRows * kH];
// W transposed to [N'=192][K=1024] bf16 hi/lo, N' = mat*64 + n
__device__ __nv_bfloat16 g_Wt_hi[192 * 1024];
__device__ __nv_bfloat16 g_Wt_lo[192 * 1024];

// ---------------------------------------------------------------------------
// HMMA m16n8k16 bf16 -> fp32 (sm_80+ baseline PTX; no arch-specific feature)
// ---------------------------------------------------------------------------
__device__ __forceinline__ void mma16816(float* d, const uint32_t* a,
                                         const uint32_t* b) {
    asm volatile(
        "mma.sync.aligned.m16n8k16.row.col.f32.bf16.bf16.f32 "
        "{%0,%1,%2,%3}, {%4,%5,%6,%7}, {%8,%9}, {%0,%1,%2,%3};"
        : "+f"(d[0]), "+f"(d[1]), "+f"(d[2]), "+f"(d[3])
        : "r"(a[0]), "r"(a[1]), "r"(a[2]), "r"(a[3]), "r"(b[0]), "r"(b[1]));
}

__device__ __forceinline__ uint32_t pack_bf16x2(float a, float b) {
    const __nv_bfloat16 ha = __float2bfloat16(a);
    const __nv_bfloat16 hb = __float2bfloat16(b);
    return (uint32_t)__bfloat16_as_ushort(ha) |
           ((uint32_t)__bfloat16_as_ushort(hb) << 16);
}
__device__ __forceinline__ uint32_t pack_bf16x2_lo(float a, float b) {
    const float ra = a - __bfloat162float(__float2bfloat16(a));
    const float rb = b - __bfloat162float(__float2bfloat16(b));
    return pack_bf16x2(ra, rb);
}

// ---------------------------------------------------------------------------
// Prep: W[k][n] fp32 -> Wt[n'][k] bf16 hi/lo
// ---------------------------------------------------------------------------
__global__ void wprep_kernel(const float* __restrict__ Wq,
                             const float* __restrict__ Wk,
                             const float* __restrict__ Wv) {
    const int idx = blockIdx.x * 256 + threadIdx.x;   // < 192*1024
    const int np = idx >> 10, k = idx & 1023;
    const int mat = np >> 6, n = np & 63;
    const float* W = (mat == 0) ? Wq : (mat == 1) ? Wk : Wv;
    const float v = W[k * 64 + n];
    const __nv_bfloat16 h = __float2bfloat16(v);
    g_Wt_hi[idx] = h;
    g_Wt_lo[idx] = __float2bfloat16(v - __bfloat162float(h));
}

// ---------------------------------------------------------------------------
// QKV GEMM: D[32768,192] = X[32768,1024] * W[1024,192] (+bias),
// 3-term bf16 split on HMMA. CTA: 128 rows x 192 cols, 512 threads
// (16 warps, warp tile 32x48). K chunked by 32, double-buffered smem,
// X staged ONCE per chunk (hi+lo derived in-register).
// ---------------------------------------------------------------------------
__global__ __launch_bounds__(512, 1)
void qkv_mma_kernel(const float* __restrict__ x,
                    const float* __restrict__ bq,
                    const float* __restrict__ bk,
                    const float* __restrict__ bv) {
    extern __shared__ __align__(16) char sm[];
    const int tid  = threadIdx.x;
    const int lane = tid & 31;
    const int w    = tid >> 5;
    const int m0   = (w >> 2) * 32;   // warp row within CTA tile
    const int n0   = (w & 3) * 48;    // warp col within CTA tile
    const int row0 = blockIdx.x * 128;

    float acc[2][6][4];
#pragma unroll
    for (int mf = 0; mf < 2; ++mf)
#pragma unroll
        for (int nf = 0; nf < 6; ++nf)
#pragma unroll
            for (int i = 0; i < 4; ++i) acc[mf][nf][i] = 0.f;

    // prefetch registers
    float4 xr[2];
    uint2 whr[3], wlr[3];

    auto ldg_chunk = [&](int k0) {
#pragma unroll
        for (int it = 0; it < 2; ++it) {
            const int e4 = tid + it * 512;          // 1024 float4 = 128x8
            const int m = e4 >> 3, k4 = (e4 & 7) * 4;
            xr[it] = *reinterpret_cast<const float4*>(
                &x[(size_t)(row0 + m) * kC + k0 + k4]);
        }
#pragma unroll
        for (int it = 0; it < 3; ++it) {
            const int g = tid + it * 512;           // 1536 uint2 = 192x8
            const int n = g >> 3, j = g & 7;
            whr[it] = *reinterpret_cast<const uint2*>(g_Wt_hi + n * 1024 + k0 + j * 4);
            wlr[it] = *reinterpret_cast<const uint2*>(g_Wt_lo + n * 1024 + k0 + j * 4);
        }
    };
    auto sts_chunk = [&](char* buf) {
#pragma unroll
        for (int it = 0; it < 2; ++it) {
            const int e4 = tid + it * 512;
            const int m = e4 >> 3, j = e4 & 7;
            const float4 v = xr[it];
            uint2 hv, lv;
            hv.x = pack_bf16x2(v.x, v.y);
            hv.y = pack_bf16x2(v.z, v.w);
            lv.x = pack_bf16x2_lo(v.x, v.y);
            lv.y = pack_bf16x2_lo(v.z, v.w);
            *reinterpret_cast<uint2*>(buf + OFF_AHI + m * 80 + j * 8) = hv;
            *reinterpret_cast<uint2*>(buf + OFF_ALO + m * 80 + j * 8) = lv;
        }
#pragma unroll
        for (int it = 0; it < 3; ++it) {
            const int g = tid + it * 512;
            const int n = g >> 3, j = g & 7;
            *reinterpret_cast<uint2*>(buf + OFF_BHI + n * 80 + j * 8) = whr[it];
            *reinterpret_cast<uint2*>(buf + OFF_BLO + n * 80 + j * 8) = wlr[it];
        }
    };

    ldg_chunk(0);
    sts_chunk(sm);
    __syncthreads();

    for (int ch = 0; ch < 32; ++ch) {
        if (ch + 1 < 32) ldg_chunk((ch + 1) * 32);   // overlap LDG with MMA
        char* buf = sm + (ch & 1) * BUFB;

#pragma unroll
        for (int ks = 0; ks < 2; ++ks) {
            const int kk = ks * 16;
            // A fragments (hi & lo) for 2 m-frags
            uint32_t ah[2][4], al[2][4];
#pragma unroll
            for (int mf = 0; mf < 2; ++mf) {
                const int row = m0 + mf * 16 + (lane >> 2);
                const int base = row * 80 + kk * 2 + (lane & 3) * 4;
                const char* A = buf + OFF_AHI;
                ah[mf][0] = *reinterpret_cast<const uint32_t*>(A + base);
                ah[mf][1] = *reinterpret_cast<const uint32_t*>(A + base + 640);
                ah[mf][2] = *reinterpret_cast<const uint32_t*>(A + base + 16);
                ah[mf][3] = *reinterpret_cast<const uint32_t*>(A + base + 656);
                const char* B = buf + OFF_ALO;
                al[mf][0] = *reinterpret_cast<const uint32_t*>(B + base);
                al[mf][1] = *reinterpret_cast<const uint32_t*>(B + base + 640);
                al[mf][2] = *reinterpret_cast<const uint32_t*>(B + base + 16);
                al[mf][3] = *reinterpret_cast<const uint32_t*>(B + base + 656);
            }
            // B fragments in halves of 3 n-frags (register pressure)
#pragma unroll
            for (int half = 0; half < 2; ++half) {
                uint32_t bh[3][2], bl[3][2];
#pragma unroll
                for (int i = 0; i < 3; ++i) {
                    const int nf = half * 3 + i;
                    const int rowb = n0 + nf * 8 + (lane >> 2);
                    const int bb = rowb * 80 + kk * 2 + (lane & 3) * 4;
                    bh[i][0] = *reinterpret_cast<const uint32_t*>(buf + OFF_BHI + bb);
                    bh[i][1] = *reinterpret_cast<const uint32_t*>(buf + OFF_BHI + bb + 16);
                    bl[i][0] = *reinterpret_cast<const uint32_t*>(buf + OFF_BLO + bb);
                    bl[i][1] = *reinterpret_cast<const uint32_t*>(buf + OFF_BLO + bb + 16);
                }
#pragma unroll
                for (int mf = 0; mf < 2; ++mf)
#pragma unroll
                    for (int i = 0; i < 3; ++i) {
                        const int nf = half * 3 + i;
                        mma16816(acc[mf][nf], ah[mf], bh[i]);
                        mma16816(acc[mf][nf], ah[mf], bl[i]);
                        mma16816(acc[mf][nf], al[mf], bh[i]);
                    }
            }
        }

        if (ch + 1 < 32) {
            __syncthreads();                        // all reads of next buf done (prev iter)
            sts_chunk(sm + ((ch + 1) & 1) * BUFB);
            __syncthreads();                        // next buf visible before its compute
        }
    }

    // ---- epilogue: +bias, scatter to g_Q / g_K / g_V ----
#pragma unroll
    for (int mf = 0; mf < 2; ++mf) {
        const int rg = row0 + m0 + mf * 16 + (lane >> 2);
#pragma unroll
        for (int nf = 0; nf < 6; ++nf) {
            const int col = n0 + nf * 8 + (lane & 3) * 2;
            const int mat = col >> 6, h = col & 63;
            const float* bias = (mat == 0) ? bq : (mat == 1) ? bk : bv;
            float* base = (mat == 0) ? g_Q : (mat == 1) ? g_K : g_V;
            const float b0 = bias[h], b1 = bias[h + 1];
            float2 v0, v1;
            v0.x = acc[mf][nf][0] + b0;
            v0.y = acc[mf][nf][1] + b1;
            v1.x = acc[mf][nf][2] + b0;
            v1.y = acc[mf][nf][3] + b1;
            *reinterpret_cast<float2*>(base + (size_t)rg * kH + h) = v0;
            *reinterpret_cast<float2*>(base + (size_t)(rg + 8) * kH + h) = v1;
        }
    }
}

// ---------------------------------------------------------------------------
// Kernel 2: causal flash attention, fp32 (unchanged known-good; next target)
// ---------------------------------------------------------------------------
__global__ __launch_bounds__(256, 2)
void attn_kernel(float* __restrict__ out) {
    extern __shared__ float smf[];
    float* Qs = smf;
    float* Ks = smf + 64 * LD;
    float* Vs = smf + 2 * 64 * LD;
    float* Ps = smf + 3 * 64 * LD;

    const int tid = threadIdx.x;
    const int tx = tid & 15;
    const int ty = tid >> 4;
    const int b  = blockIdx.x & 15;
    const int qt = (kQT - 1) - (blockIdx.x >> 4);
    const int q0 = qt * 64;

    const float* Qg = g_Q + (size_t)b * kT * kH;
    const float* Kg = g_K + (size_t)b * kT * kH;
    const float* Vg = g_V + (size_t)b * kT * kH;

#pragma unroll
    for (int i = 0; i < 16; ++i) {
        const int idx = tid + i * 256;
        const int r = idx >> 6, h = idx & 63;
        Qs[r * LD + h] = Qg[(q0 + r) * kH + h];
    }

    float m[4], l[4], o[4][4];
#pragma unroll
    for (int r = 0; r < 4; ++r) {
        m[r] = -1e30f;
        l[r] = 0.f;
#pragma unroll
        for (int c = 0; c < 4; ++c) o[r][c] = 0.f;
    }

    for (int jt = 0; jt <= qt; ++jt) {
        const int j0 = jt * 64;
        __syncthreads();
#pragma unroll
        for (int i = 0; i < 16; ++i) {
            const int idx = tid + i * 256;
            const int r = idx >> 6, h = idx & 63;
            Ks[r * LD + h] = Kg[(j0 + r) * kH + h];
            Vs[r * LD + h] = Vg[(j0 + r) * kH + h];
        }
        __syncthreads();

        float s[4][4];
#pragma unroll
        for (int r = 0; r < 4; ++r)
#pragma unroll
            for (int c = 0; c < 4; ++c) s[r][c] = 0.f;

#pragma unroll 4
        for (int h = 0; h < 64; h += 4) {
            float4 qv[4], kv[4];
#pragma unroll
            for (int r = 0; r < 4; ++r)
                qv[r] = *reinterpret_cast<const float4*>(&Qs[(ty * 4 + r) * LD + h]);
#pragma unroll
            for (int c = 0; c < 4; ++c)
                kv[c] = *reinterpret_cast<const float4*>(&Ks[(c * 16 + tx) * LD + h]);
#pragma unroll
            for (int r = 0; r < 4; ++r)
#pragma unroll
                for (int c = 0; c < 4; ++c) {
                    s[r][c] = fmaf(qv[r].x, kv[c].x, s[r][c]);
                    s[r][c] = fmaf(qv[r].y, kv[c].y, s[r][c]);
                    s[r][c] = fmaf(qv[r].z, kv[c].z, s[r][c]);
                    s[r][c] = fmaf(qv[r].w, kv[c].w, s[r][c]);
                }
        }

        const float scale = 0.125f;
        float rowmax[4];
#pragma unroll
        for (int r = 0; r < 4; ++r) {
            const int qg = q0 + ty * 4 + r;
            float rm = -1e30f;
#pragma unroll
            for (int c = 0; c < 4; ++c) {
                const int kg = j0 + c * 16 + tx;
                const float v = (kg <= qg) ? s[r][c] * scale : -1e30f;
                s[r][c] = v;
                rm = fmaxf(rm, v);
            }
            rowmax[r] = rm;
        }
#pragma unroll
        for (int off = 1; off < 16; off <<= 1)
#pragma unroll
            for (int r = 0; r < 4; ++r)
                rowmax[r] = fmaxf(rowmax[r], __shfl_xor_sync(0xffffffffu, rowmax[r], off));

        float alpha[4], rowsum[4];
#pragma unroll
        for (int r = 0; r < 4; ++r) {
            const float mn = fmaxf(m[r], rowmax[r]);
            alpha[r] = __expf(m[r] - mn);
            m[r] = mn;
            float rs = 0.f;
#pragma unroll
            for (int c = 0; c < 4; ++c) {
                const float p = __expf(s[r][c] - mn);
                Ps[(ty * 4 + r) * LD + (c * 16 + tx)] = p;
                rs += p;
            }
            rowsum[r] = rs;
        }
#pragma unroll
        for (int off = 1; off < 16; off <<= 1)
#pragma unroll
            for (int r = 0; r < 4; ++r)
                rowsum[r] += __shfl_xor_sync(0xffffffffu, rowsum[r], off);
#pragma unroll
        for (int r = 0; r < 4; ++r) {
            l[r] = l[r] * alpha[r] + rowsum[r];
#pragma unroll
            for (int c = 0; c < 4; ++c) o[r][c] *= alpha[r];
        }
        __syncthreads();

#pragma unroll 4
        for (int j = 0; j < 64; j += 4) {
            float vvf[4][4];
#pragma unroll
            for (int jj = 0; jj < 4; ++jj) {
                const float4 vv = *reinterpret_cast<const float4*>(&Vs[(j + jj) * LD + tx * 4]);
                vvf[jj][0] = vv.x; vvf[jj][1] = vv.y; vvf[jj][2] = vv.z; vvf[jj][3] = vv.w;
            }
#pragma unroll
            for (int r = 0; r < 4; ++r) {
                const float4 p = *reinterpret_cast<const float4*>(&Ps[(ty * 4 + r) * LD + j]);
                const float pr[4] = {p.x, p.y, p.z, p.w};
#pragma unroll
                for (int jj = 0; jj < 4; ++jj) {
                    o[r][0] = fmaf(pr[jj], vvf[jj][0], o[r][0]);
                    o[r][1] = fmaf(pr[jj], vvf[jj][1], o[r][1]);
                    o[r][2] = fmaf(pr[jj], vvf[jj][2], o[r][2]);
                    o[r][3] = fmaf(pr[jj], vvf[jj][3], o[r][3]);
                }
            }
        }
    }

#pragma unroll
    for (int r = 0; r < 4; ++r) {
        const float inv = 1.0f / l[r];
        const size_t row = (size_t)b * kT + q0 + ty * 4 + r;
        float4 res;
        res.x = o[r][0] * inv;
        res.y = o[r][1] * inv;
        res.z = o[r][2] * inv;
        res.w = o[r][3] * inv;
        *reinterpret_cast<float4*>(&out[row * kH + tx * 4]) = res;
    }
}

// ---------------------------------------------------------------------------
extern "C" void kernel_launch(void* const* d_in, const int* in_sizes, int n_in,
                              void* d_out, int out_size) {
    (void)in_sizes; (void)n_in; (void)out_size;
    const float* x  = (const float*)d_in[0];
    const float* Wq = (const float*)d_in[1];
    const float* bq = (const float*)d_in[2];
    const float* Wk = (const float*)d_in[3];
    const float* bk = (const float*)d_in[4];
    const float* Wv = (const float*)d_in[5];
    const float* bv = (const float*)d_in[6];
    float* out = (float*)d_out;

    // 1) W transpose + bf16 split
    wprep_kernel<<<(192 * 1024) / 256, 256>>>(Wq, Wk, Wv);

    // 2) QKV GEMM on HMMA (mma.sync bf16, 3-term split)
    cudaFuncSetAttribute(qkv_mma_kernel, cudaFuncAttributeMaxDynamicSharedMemorySize,
                         QKV_SMEM);
    qkv_mma_kernel<<<kRows / 128, 512, QKV_SMEM>>>(x, bq, bk, bv);

    // 3) causal flash attention (fp32, unchanged)
    constexpr int kAttnSmem = 4 * 64 * LD * (int)sizeof(float);
    cudaFuncSetAttribute(attn_kernel, cudaFuncAttributeMaxDynamicSharedMemorySize,
                         kAttnSmem);
    attn_kernel<<<kB * kQT, 256, kAttnSmem>>>(out);
}

// round 4
// speedup vs baseline: 1.9947x; 1.1575x over previous
#include <cuda_runtime.h>
#include <cuda_bf16.h>
#include <cstdint>

// ---------------------------------------------------------------------------
// Problem constants
// ---------------------------------------------------------------------------
namespace {
constexpr int kB = 16;
constexpr int kT = 2048;
constexpr int kC = 1024;
constexpr int kH = 64;
constexpr int kRows = kB * kT;     // 32768
constexpr int kQT = kT / 64;       // 32 q-tiles per batch

// QKV GEMM smem layout (bytes), 80B-padded rows (validated R3)
constexpr int OFF_AHI = 0;
constexpr int OFF_ALO = 10240;
constexpr int OFF_BHI = 20480;
constexpr int OFF_BLO = 35840;
constexpr int BUFB    = 51200;
constexpr int QKV_SMEM = 2 * BUFB;

// Attention smem layout (bytes), 144B-padded rows (64 bf16 + pad)
constexpr int APAD = 144;
constexpr int A_QHI = 0;
constexpr int A_QLO = 9216;
constexpr int A_KHI = 18432;
constexpr int A_KLO = 27648;
constexpr int A_VHI = 36864;
constexpr int A_VLO = 46080;
constexpr int ATTN_SMEM = 55296;
}

// Scratch (__device__ globals: allocation-free)
__device__ float g_Q[kRows * kH];
__device__ float g_K[kRows * kH];
__device__ float g_V[kRows * kH];
__device__ __nv_bfloat16 g_Wt_hi[192 * 1024];
__device__ __nv_bfloat16 g_Wt_lo[192 * 1024];

// ---------------------------------------------------------------------------
// HMMA m16n8k16 bf16 -> fp32 (sm_80+ baseline PTX)
// ---------------------------------------------------------------------------
__device__ __forceinline__ void mma16816(float* d, const uint32_t* a,
                                         const uint32_t* b) {
    asm volatile(
        "mma.sync.aligned.m16n8k16.row.col.f32.bf16.bf16.f32 "
        "{%0,%1,%2,%3}, {%4,%5,%6,%7}, {%8,%9}, {%0,%1,%2,%3};"
        : "+f"(d[0]), "+f"(d[1]), "+f"(d[2]), "+f"(d[3])
        : "r"(a[0]), "r"(a[1]), "r"(a[2]), "r"(a[3]), "r"(b[0]), "r"(b[1]));
}

__device__ __forceinline__ uint32_t pack_bf16x2(float a, float b) {
    const __nv_bfloat16 ha = __float2bfloat16(a);
    const __nv_bfloat16 hb = __float2bfloat16(b);
    return (uint32_t)__bfloat16_as_ushort(ha) |
           ((uint32_t)__bfloat16_as_ushort(hb) << 16);
}
__device__ __forceinline__ uint32_t pack_bf16x2_lo(float a, float b) {
    const float ra = a - __bfloat162float(__float2bfloat16(a));
    const float rb = b - __bfloat162float(__float2bfloat16(b));
    return pack_bf16x2(ra, rb);
}

// ---------------------------------------------------------------------------
// Prep: W[k][n] fp32 -> Wt[n'][k] bf16 hi/lo
// ---------------------------------------------------------------------------
__global__ void wprep_kernel(const float* __restrict__ Wq,
                             const float* __restrict__ Wk,
                             const float* __restrict__ Wv) {
    const int idx = blockIdx.x * 256 + threadIdx.x;
    const int np = idx >> 10, k = idx & 1023;
    const int mat = np >> 6, n = np & 63;
    const float* W = (mat == 0) ? Wq : (mat == 1) ? Wk : Wv;
    const float v = W[k * 64 + n];
    const __nv_bfloat16 h = __float2bfloat16(v);
    g_Wt_hi[idx] = h;
    g_Wt_lo[idx] = __float2bfloat16(v - __bfloat162float(h));
}

// ---------------------------------------------------------------------------
// QKV GEMM (unchanged from R3 — validated, ~140us)
// ---------------------------------------------------------------------------
__global__ __launch_bounds__(512, 1)
void qkv_mma_kernel(const float* __restrict__ x,
                    const float* __restrict__ bq,
                    const float* __restrict__ bk,
                    const float* __restrict__ bv) {
    extern __shared__ __align__(16) char sm[];
    const int tid  = threadIdx.x;
    const int lane = tid & 31;
    const int w    = tid >> 5;
    const int m0   = (w >> 2) * 32;
    const int n0   = (w & 3) * 48;
    const int row0 = blockIdx.x * 128;

    float acc[2][6][4];
#pragma unroll
    for (int mf = 0; mf < 2; ++mf)
#pragma unroll
        for (int nf = 0; nf < 6; ++nf)
#pragma unroll
            for (int i = 0; i < 4; ++i) acc[mf][nf][i] = 0.f;

    float4 xr[2];
    uint2 whr[3], wlr[3];

    auto ldg_chunk = [&](int k0) {
#pragma unroll
        for (int it = 0; it < 2; ++it) {
            const int e4 = tid + it * 512;
            const int m = e4 >> 3, k4 = (e4 & 7) * 4;
            xr[it] = *reinterpret_cast<const float4*>(
                &x[(size_t)(row0 + m) * kC + k0 + k4]);
        }
#pragma unroll
        for (int it = 0; it < 3; ++it) {
            const int g = tid + it * 512;
            const int n = g >> 3, j = g & 7;
            whr[it] = *reinterpret_cast<const uint2*>(g_Wt_hi + n * 1024 + k0 + j * 4);
            wlr[it] = *reinterpret_cast<const uint2*>(g_Wt_lo + n * 1024 + k0 + j * 4);
        }
    };
    auto sts_chunk = [&](char* buf) {
#pragma unroll
        for (int it = 0; it < 2; ++it) {
            const int e4 = tid + it * 512;
            const int m = e4 >> 3, j = e4 & 7;
            const float4 v = xr[it];
            uint2 hv, lv;
            hv.x = pack_bf16x2(v.x, v.y);
            hv.y = pack_bf16x2(v.z, v.w);
            lv.x = pack_bf16x2_lo(v.x, v.y);
            lv.y = pack_bf16x2_lo(v.z, v.w);
            *reinterpret_cast<uint2*>(buf + OFF_AHI + m * 80 + j * 8) = hv;
            *reinterpret_cast<uint2*>(buf + OFF_ALO + m * 80 + j * 8) = lv;
        }
#pragma unroll
        for (int it = 0; it < 3; ++it) {
            const int g = tid + it * 512;
            const int n = g >> 3, j = g & 7;
            *reinterpret_cast<uint2*>(buf + OFF_BHI + n * 80 + j * 8) = whr[it];
            *reinterpret_cast<uint2*>(buf + OFF_BLO + n * 80 + j * 8) = wlr[it];
        }
    };

    ldg_chunk(0);
    sts_chunk(sm);
    __syncthreads();

    for (int ch = 0; ch < 32; ++ch) {
        if (ch + 1 < 32) ldg_chunk((ch + 1) * 32);
        char* buf = sm + (ch & 1) * BUFB;

#pragma unroll
        for (int ks = 0; ks < 2; ++ks) {
            const int kk = ks * 16;
            uint32_t ah[2][4], al[2][4];
#pragma unroll
            for (int mf = 0; mf < 2; ++mf) {
                const int row = m0 + mf * 16 + (lane >> 2);
                const int base = row * 80 + kk * 2 + (lane & 3) * 4;
                const char* A = buf + OFF_AHI;
                ah[mf][0] = *reinterpret_cast<const uint32_t*>(A + base);
                ah[mf][1] = *reinterpret_cast<const uint32_t*>(A + base + 640);
                ah[mf][2] = *reinterpret_cast<const uint32_t*>(A + base + 16);
                ah[mf][3] = *reinterpret_cast<const uint32_t*>(A + base + 656);
                const char* B = buf + OFF_ALO;
                al[mf][0] = *reinterpret_cast<const uint32_t*>(B + base);
                al[mf][1] = *reinterpret_cast<const uint32_t*>(B + base + 640);
                al[mf][2] = *reinterpret_cast<const uint32_t*>(B + base + 16);
                al[mf][3] = *reinterpret_cast<const uint32_t*>(B + base + 656);
            }
#pragma unroll
            for (int half = 0; half < 2; ++half) {
                uint32_t bh[3][2], bl[3][2];
#pragma unroll
                for (int i = 0; i < 3; ++i) {
                    const int nf = half * 3 + i;
                    const int rowb = n0 + nf * 8 + (lane >> 2);
                    const int bb = rowb * 80 + kk * 2 + (lane & 3) * 4;
                    bh[i][0] = *reinterpret_cast<const uint32_t*>(buf + OFF_BHI + bb);
                    bh[i][1] = *reinterpret_cast<const uint32_t*>(buf + OFF_BHI + bb + 16);
                    bl[i][0] = *reinterpret_cast<const uint32_t*>(buf + OFF_BLO + bb);
                    bl[i][1] = *reinterpret_cast<const uint32_t*>(buf + OFF_BLO + bb + 16);
                }
#pragma unroll
                for (int mf = 0; mf < 2; ++mf)
#pragma unroll
                    for (int i = 0; i < 3; ++i) {
                        const int nf = half * 3 + i;
                        mma16816(acc[mf][nf], ah[mf], bh[i]);
                        mma16816(acc[mf][nf], ah[mf], bl[i]);
                        mma16816(acc[mf][nf], al[mf], bh[i]);
                    }
            }
        }

        if (ch + 1 < 32) {
            __syncthreads();
            sts_chunk(sm + ((ch + 1) & 1) * BUFB);
            __syncthreads();
        }
    }

#pragma unroll
    for (int mf = 0; mf < 2; ++mf) {
        const int rg = row0 + m0 + mf * 16 + (lane >> 2);
#pragma unroll
        for (int nf = 0; nf < 6; ++nf) {
            const int col = n0 + nf * 8 + (lane & 3) * 2;
            const int mat = col >> 6, h = col & 63;
            const float* bias = (mat == 0) ? bq : (mat == 1) ? bk : bv;
            float* base = (mat == 0) ? g_Q : (mat == 1) ? g_K : g_V;
            const float b0 = bias[h], b1 = bias[h + 1];
            float2 v0, v1;
            v0.x = acc[mf][nf][0] + b0;
            v0.y = acc[mf][nf][1] + b1;
            v1.x = acc[mf][nf][2] + b0;
            v1.y = acc[mf][nf][3] + b1;
            *reinterpret_cast<float2*>(base + (size_t)rg * kH + h) = v0;
            *reinterpret_cast<float2*>(base + (size_t)(rg + 8) * kH + h) = v1;
        }
    }
}

// ---------------------------------------------------------------------------
// Kernel 2: causal flash attention on HMMA, 3-term bf16 split.
// CTA = (batch, 64-row q-tile), 128 threads = 4 warps, warp tile m16 x n64.
// P stays in registers (accumulator frag == A frag layout).
// ---------------------------------------------------------------------------
__global__ __launch_bounds__(128, 4)
void attn_mma_kernel(float* __restrict__ out) {
    extern __shared__ __align__(16) char sma[];
    char* Qh = sma + A_QHI;
    char* Ql = sma + A_QLO;
    char* Kh = sma + A_KHI;
    char* Kl = sma + A_KLO;
    char* Vh = sma + A_VHI;
    char* Vl = sma + A_VLO;

    const int tid  = threadIdx.x;
    const int lane = tid & 31;
    const int w    = tid >> 5;
    const int b    = blockIdx.x & 15;
    const int qt   = (kQT - 1) - (blockIdx.x >> 4);   // heaviest first
    const int q0   = qt * 64;
    const int m0w  = w * 16;
    const int r1   = lane >> 2;       // 0..7
    const int kq   = lane & 3;        // 0..3

    // ---- load Q tile once: fp32 -> bf16 hi/lo ----
    const float* Qg = g_Q + ((size_t)b * kT + q0) * kH;
#pragma unroll
    for (int it = 0; it < 8; ++it) {
        const int idx = tid + it * 128;
        const int r = idx >> 4, h4 = (idx & 15) * 4;
        const float4 v = *reinterpret_cast<const float4*>(&Qg[r * kH + h4]);
        uint2 hv, lv;
        hv.x = pack_bf16x2(v.x, v.y);
        hv.y = pack_bf16x2(v.z, v.w);
        lv.x = pack_bf16x2_lo(v.x, v.y);
        lv.y = pack_bf16x2_lo(v.z, v.w);
        *reinterpret_cast<uint2*>(Qh + r * APAD + h4 * 2) = hv;
        *reinterpret_cast<uint2*>(Ql + r * APAD + h4 * 2) = lv;
    }

    float o[8][4];
#pragma unroll
    for (int nf = 0; nf < 8; ++nf)
#pragma unroll
        for (int c = 0; c < 4; ++c) o[nf][c] = 0.f;
    float mrow[2] = {-1e30f, -1e30f};
    float lrow[2] = {0.f, 0.f};

    for (int jt = 0; jt <= qt; ++jt) {
        const int j0 = jt * 64;
        const float* Kg = g_K + ((size_t)b * kT + j0) * kH;
        const float* Vg = g_V + ((size_t)b * kT + j0) * kH;

        __syncthreads();   // prior iteration's smem reads done
        // ---- stage K (as-is) and V (transposed) tiles, bf16 hi/lo ----
#pragma unroll
        for (int it = 0; it < 8; ++it) {
            const int idx = tid + it * 128;
            const int r = idx >> 4, h4 = (idx & 15) * 4;
            const float4 kv = *reinterpret_cast<const float4*>(&Kg[r * kH + h4]);
            uint2 hv, lv;
            hv.x = pack_bf16x2(kv.x, kv.y);
            hv.y = pack_bf16x2(kv.z, kv.w);
            lv.x = pack_bf16x2_lo(kv.x, kv.y);
            lv.y = pack_bf16x2_lo(kv.z, kv.w);
            *reinterpret_cast<uint2*>(Kh + r * APAD + h4 * 2) = hv;
            *reinterpret_cast<uint2*>(Kl + r * APAD + h4 * 2) = lv;

            const float4 vv = *reinterpret_cast<const float4*>(&Vg[r * kH + h4]);
            const float vf[4] = {vv.x, vv.y, vv.z, vv.w};
#pragma unroll
            for (int i = 0; i < 4; ++i) {
                const __nv_bfloat16 hh = __float2bfloat16(vf[i]);
                const __nv_bfloat16 ll =
                    __float2bfloat16(vf[i] - __bfloat162float(hh));
                *reinterpret_cast<__nv_bfloat16*>(Vh + (h4 + i) * APAD + r * 2) = hh;
                *reinterpret_cast<__nv_bfloat16*>(Vl + (h4 + i) * APAD + r * 2) = ll;
            }
        }
        __syncthreads();

        // ---- S = Q K^T (3-term split) ----
        float s[8][4];
#pragma unroll
        for (int nf = 0; nf < 8; ++nf)
#pragma unroll
            for (int c = 0; c < 4; ++c) s[nf][c] = 0.f;

#pragma unroll
        for (int ks = 0; ks < 4; ++ks) {
            const int abase = (m0w + r1) * APAD + ks * 32 + kq * 4;
            uint32_t ah[4], al[4];
            ah[0] = *reinterpret_cast<const uint32_t*>(Qh + abase);
            ah[1] = *reinterpret_cast<const uint32_t*>(Qh + abase + 8 * APAD);
            ah[2] = *reinterpret_cast<const uint32_t*>(Qh + abase + 16);
            ah[3] = *reinterpret_cast<const uint32_t*>(Qh + abase + 8 * APAD + 16);
            al[0] = *reinterpret_cast<const uint32_t*>(Ql + abase);
            al[1] = *reinterpret_cast<const uint32_t*>(Ql + abase + 8 * APAD);
            al[2] = *reinterpret_cast<const uint32_t*>(Ql + abase + 16);
            al[3] = *reinterpret_cast<const uint32_t*>(Ql + abase + 8 * APAD + 16);
#pragma unroll
            for (int nf = 0; nf < 8; ++nf) {
                const int bbase = (nf * 8 + r1) * APAD + ks * 32 + kq * 4;
                uint32_t bh[2], bl[2];
                bh[0] = *reinterpret_cast<const uint32_t*>(Kh + bbase);
                bh[1] = *reinterpret_cast<const uint32_t*>(Kh + bbase + 16);
                bl[0] = *reinterpret_cast<const uint32_t*>(Kl + bbase);
                bl[1] = *reinterpret_cast<const uint32_t*>(Kl + bbase + 16);
                mma16816(s[nf], ah, bh);
                mma16816(s[nf], ah, bl);
                mma16816(s[nf], al, bh);
            }
        }

        // ---- scale + causal mask + online softmax ----
        const float sc = 0.125f;
        const int qg1 = q0 + m0w + r1;
        const int qg2 = qg1 + 8;
        float mx1 = -1e30f, mx2 = -1e30f;
#pragma unroll
        for (int nf = 0; nf < 8; ++nf) {
            const int kg0 = j0 + nf * 8 + kq * 2;
            const float v0 = (kg0     <= qg1) ? s[nf][0] * sc : -1e30f;
            const float v1 = (kg0 + 1 <= qg1) ? s[nf][1] * sc : -1e30f;
            const float v2 = (kg0     <= qg2) ? s[nf][2] * sc : -1e30f;
            const float v3 = (kg0 + 1 <= qg2) ? s[nf][3] * sc : -1e30f;
            s[nf][0] = v0; s[nf][1] = v1; s[nf][2] = v2; s[nf][3] = v3;
            mx1 = fmaxf(mx1, fmaxf(v0, v1));
            mx2 = fmaxf(mx2, fmaxf(v2, v3));
        }
        mx1 = fmaxf(mx1, __shfl_xor_sync(0xffffffffu, mx1, 1));
        mx1 = fmaxf(mx1, __shfl_xor_sync(0xffffffffu, mx1, 2));
        mx2 = fmaxf(mx2, __shfl_xor_sync(0xffffffffu, mx2, 1));
        mx2 = fmaxf(mx2, __shfl_xor_sync(0xffffffffu, mx2, 2));

        const float mn1 = fmaxf(mrow[0], mx1);
        const float mn2 = fmaxf(mrow[1], mx2);
        const float a1 = __expf(mrow[0] - mn1);
        const float a2 = __expf(mrow[1] - mn2);
        mrow[0] = mn1; mrow[1] = mn2;

        float rs1 = 0.f, rs2 = 0.f;
#pragma unroll
        for (int nf = 0; nf < 8; ++nf) {
            s[nf][0] = __expf(s[nf][0] - mn1);
            s[nf][1] = __expf(s[nf][1] - mn1);
            s[nf][2] = __expf(s[nf][2] - mn2);
            s[nf][3] = __expf(s[nf][3] - mn2);
            rs1 += s[nf][0] + s[nf][1];
            rs2 += s[nf][2] + s[nf][3];
        }
        rs1 += __shfl_xor_sync(0xffffffffu, rs1, 1);
        rs1 += __shfl_xor_sync(0xffffffffu, rs1, 2);
        rs2 += __shfl_xor_sync(0xffffffffu, rs2, 1);
        rs2 += __shfl_xor_sync(0xffffffffu, rs2, 2);
        lrow[0] = lrow[0] * a1 + rs1;
        lrow[1] = lrow[1] * a2 + rs2;
#pragma unroll
        for (int nf = 0; nf < 8; ++nf) {
            o[nf][0] *= a1; o[nf][1] *= a1;
            o[nf][2] *= a2; o[nf][3] *= a2;
        }

        // ---- O += P V : P packed straight from accumulator frags ----
#pragma unroll
        for (int ks = 0; ks < 4; ++ks) {
            uint32_t pa_h[4], pa_l[4];
            pa_h[0] = pack_bf16x2(s[2 * ks][0], s[2 * ks][1]);
            pa_h[1] = pack_bf16x2(s[2 * ks][2], s[2 * ks][3]);
            pa_h[2] = pack_bf16x2(s[2 * ks + 1][0], s[2 * ks + 1][1]);
            pa_h[3] = pack_bf16x2(s[2 * ks + 1][2], s[2 * ks + 1][3]);
            pa_l[0] = pack_bf16x2_lo(s[2 * ks][0], s[2 * ks][1]);
            pa_l[1] = pack_bf16x2_lo(s[2 * ks][2], s[2 * ks][3]);
            pa_l[2] = pack_bf16x2_lo(s[2 * ks + 1][0], s[2 * ks + 1][1]);
            pa_l[3] = pack_bf16x2_lo(s[2 * ks + 1][2], s[2 * ks + 1][3]);
#pragma unroll
            for (int nf = 0; nf < 8; ++nf) {
                const int bbase = (nf * 8 + r1) * APAD + ks * 32 + kq * 4;
                uint32_t vh2[2], vl2[2];
                vh2[0] = *reinterpret_cast<const uint32_t*>(Vh + bbase);
                vh2[1] = *reinterpret_cast<const uint32_t*>(Vh + bbase + 16);
                vl2[0] = *reinterpret_cast<const uint32_t*>(Vl + bbase);
                vl2[1] = *reinterpret_cast<const uint32_t*>(Vl + bbase + 16);
                mma16816(o[nf], pa_h, vh2);
                mma16816(o[nf], pa_h, vl2);
                mma16816(o[nf], pa_l, vh2);
            }
        }
    }

    // ---- epilogue: normalize + store ----
    const float inv1 = 1.0f / lrow[0];
    const float inv2 = 1.0f / lrow[1];
    float* og = out + ((size_t)b * kT + q0 + m0w) * kH;
#pragma unroll
    for (int nf = 0; nf < 8; ++nf) {
        const int col = nf * 8 + kq * 2;
        float2 v0, v1;
        v0.x = o[nf][0] * inv1; v0.y = o[nf][1] * inv1;
        v1.x = o[nf][2] * inv2; v1.y = o[nf][3] * inv2;
        *reinterpret_cast<float2*>(&og[r1 * kH + col]) = v0;
        *reinterpret_cast<float2*>(&og[(r1 + 8) * kH + col]) = v1;
    }
}

// ---------------------------------------------------------------------------
extern "C" void kernel_launch(void* const* d_in, const int* in_sizes, int n_in,
                              void* d_out, int out_size) {
    (void)in_sizes; (void)n_in; (void)out_size;
    const float* x  = (const float*)d_in[0];
    const float* Wq = (const float*)d_in[1];
    const float* bq = (const float*)d_in[2];
    const float* Wk = (const float*)d_in[3];
    const float* bk = (const float*)d_in[4];
    const float* Wv = (const float*)d_in[5];
    const float* bv = (const float*)d_in[6];
    float* out = (float*)d_out;

    wprep_kernel<<<(192 * 1024) / 256, 256>>>(Wq, Wk, Wv);

    cudaFuncSetAttribute(qkv_mma_kernel, cudaFuncAttributeMaxDynamicSharedMemorySize,
                         QKV_SMEM);
    qkv_mma_kernel<<<kRows / 128, 512, QKV_SMEM>>>(x, bq, bk, bv);

    cudaFuncSetAttribute(attn_mma_kernel, cudaFuncAttributeMaxDynamicSharedMemorySize,
                         ATTN_SMEM);
    attn_mma_kernel<<<kB * kQT, 128, ATTN_SMEM>>>(out);
}

// round 5
// speedup vs baseline: 2.7839x; 1.3957x over previous
#include <cuda_runtime.h>
#include <cuda_bf16.h>
#include <cstdint>

// ---------------------------------------------------------------------------
// Problem constants
// ---------------------------------------------------------------------------
namespace {
constexpr int kB = 16;
constexpr int kT = 2048;
constexpr int kC = 1024;
constexpr int kH = 64;
constexpr int kRows = kB * kT;     // 32768
constexpr int kQT = kT / 64;       // 32 q-tiles per batch

// QKV GEMM smem layout (bytes), 80B-padded rows (validated R3)
constexpr int OFF_AHI = 0;
constexpr int OFF_ALO = 10240;
constexpr int OFF_BHI = 20480;
constexpr int OFF_BLO = 35840;
constexpr int BUFB    = 51200;
constexpr int QKV_SMEM = 2 * BUFB;

// Attention smem layout (bytes), 144B-padded rows (64 bf16 = 128B + 16B pad)
constexpr int APAD  = 144;
constexpr int A_QH  = 0;
constexpr int A_QL  = 9216;
constexpr int A_BUF = 18432;       // double-buffered K/V tiles
constexpr int BK_KH = 0;
constexpr int BK_KL = 9216;
constexpr int BK_VH = 18432;
constexpr int BK_VL = 27648;
constexpr int ABUFSZ = 36864;
constexpr int ATTN_SMEM = A_BUF + 2 * ABUFSZ;   // 92160
}

// Scratch (__device__ globals: allocation-free)
__device__ float g_V[kRows * kH];
__device__ __nv_bfloat16 g_Qh[kRows * kH], g_Ql[kRows * kH];
__device__ __nv_bfloat16 g_Kh[kRows * kH], g_Kl[kRows * kH];
__device__ __nv_bfloat16 g_VTh[kB * kH * kT], g_VTl[kB * kH * kT];
__device__ __nv_bfloat16 g_Wt_hi[192 * 1024];
__device__ __nv_bfloat16 g_Wt_lo[192 * 1024];

// ---------------------------------------------------------------------------
// PTX helpers (all baseline sm_80+ — survive compute_103 lowering)
// ---------------------------------------------------------------------------
__device__ __forceinline__ void mma16816(float* d, const uint32_t* a,
                                         const uint32_t* b) {
    asm volatile(
        "mma.sync.aligned.m16n8k16.row.col.f32.bf16.bf16.f32 "
        "{%0,%1,%2,%3}, {%4,%5,%6,%7}, {%8,%9}, {%0,%1,%2,%3};"
        : "+f"(d[0]), "+f"(d[1]), "+f"(d[2]), "+f"(d[3])
        : "r"(a[0]), "r"(a[1]), "r"(a[2]), "r"(a[3]), "r"(b[0]), "r"(b[1]));
}
__device__ __forceinline__ uint32_t pack_bf16x2(float a, float b) {
    const __nv_bfloat16 ha = __float2bfloat16(a);
    const __nv_bfloat16 hb = __float2bfloat16(b);
    return (uint32_t)__bfloat16_as_ushort(ha) |
           ((uint32_t)__bfloat16_as_ushort(hb) << 16);
}
__device__ __forceinline__ uint32_t pack_bf16x2_lo(float a, float b) {
    const float ra = a - __bfloat162float(__float2bfloat16(a));
    const float rb = b - __bfloat162float(__float2bfloat16(b));
    return pack_bf16x2(ra, rb);
}
__device__ __forceinline__ uint32_t smem_addr(const void* p) {
    return (uint32_t)__cvta_generic_to_shared(p);
}
#define CP_ASYNC16(dst, src) \
    asm volatile("cp.async.cg.shared.global [%0], [%1], 16;" \
                 :: "r"(dst), "l"(src))
#define CP_COMMIT() asm volatile("cp.async.commit_group;" ::: "memory")
#define CP_WAIT1()  asm volatile("cp.async.wait_group 1;" ::: "memory")

// ---------------------------------------------------------------------------
// Prep: W[k][n] fp32 -> Wt[n'][k] bf16 hi/lo
// ---------------------------------------------------------------------------
__global__ void wprep_kernel(const float* __restrict__ Wq,
                             const float* __restrict__ Wk,
                             const float* __restrict__ Wv) {
    const int idx = blockIdx.x * 256 + threadIdx.x;
    const int np = idx >> 10, k = idx & 1023;
    const int mat = np >> 6, n = np & 63;
    const float* W = (mat == 0) ? Wq : (mat == 1) ? Wk : Wv;
    const float v = W[k * 64 + n];
    const __nv_bfloat16 h = __float2bfloat16(v);
    g_Wt_hi[idx] = h;
    g_Wt_lo[idx] = __float2bfloat16(v - __bfloat162float(h));
}

// ---------------------------------------------------------------------------
// QKV GEMM (R3-validated mainloop). Epilogue now writes:
//   Q -> bf16 hi/lo, pre-scaled by 1/8     (g_Qh / g_Ql)
//   K -> bf16 hi/lo                        (g_Kh / g_Kl)
//   V -> fp32 (transposed+split by vtrans) (g_V)
// ---------------------------------------------------------------------------
__global__ __launch_bounds__(512, 1)
void qkv_mma_kernel(const float* __restrict__ x,
                    const float* __restrict__ bq,
                    const float* __restrict__ bk,
                    const float* __restrict__ bv) {
    extern __shared__ __align__(16) char sm[];
    const int tid  = threadIdx.x;
    const int lane = tid & 31;
    const int w    = tid >> 5;
    const int m0   = (w >> 2) * 32;
    const int n0   = (w & 3) * 48;
    const int row0 = blockIdx.x * 128;

    float acc[2][6][4];
#pragma unroll
    for (int mf = 0; mf < 2; ++mf)
#pragma unroll
        for (int nf = 0; nf < 6; ++nf)
#pragma unroll
            for (int i = 0; i < 4; ++i) acc[mf][nf][i] = 0.f;

    float4 xr[2];
    uint2 whr[3], wlr[3];

    auto ldg_chunk = [&](int k0) {
#pragma unroll
        for (int it = 0; it < 2; ++it) {
            const int e4 = tid + it * 512;
            const int m = e4 >> 3, k4 = (e4 & 7) * 4;
            xr[it] = *reinterpret_cast<const float4*>(
                &x[(size_t)(row0 + m) * kC + k0 + k4]);
        }
#pragma unroll
        for (int it = 0; it < 3; ++it) {
            const int g = tid + it * 512;
            const int n = g >> 3, j = g & 7;
            whr[it] = *reinterpret_cast<const uint2*>(g_Wt_hi + n * 1024 + k0 + j * 4);
            wlr[it] = *reinterpret_cast<const uint2*>(g_Wt_lo + n * 1024 + k0 + j * 4);
        }
    };
    auto sts_chunk = [&](char* buf) {
#pragma unroll
        for (int it = 0; it < 2; ++it) {
            const int e4 = tid + it * 512;
            const int m = e4 >> 3, j = e4 & 7;
            const float4 v = xr[it];
            uint2 hv, lv;
            hv.x = pack_bf16x2(v.x, v.y);
            hv.y = pack_bf16x2(v.z, v.w);
            lv.x = pack_bf16x2_lo(v.x, v.y);
            lv.y = pack_bf16x2_lo(v.z, v.w);
            *reinterpret_cast<uint2*>(buf + OFF_AHI + m * 80 + j * 8) = hv;
            *reinterpret_cast<uint2*>(buf + OFF_ALO + m * 80 + j * 8) = lv;
        }
#pragma unroll
        for (int it = 0; it < 3; ++it) {
            const int g = tid + it * 512;
            const int n = g >> 3, j = g & 7;
            *reinterpret_cast<uint2*>(buf + OFF_BHI + n * 80 + j * 8) = whr[it];
            *reinterpret_cast<uint2*>(buf + OFF_BLO + n * 80 + j * 8) = wlr[it];
        }
    };

    ldg_chunk(0);
    sts_chunk(sm);
    __syncthreads();

    for (int ch = 0; ch < 32; ++ch) {
        if (ch + 1 < 32) ldg_chunk((ch + 1) * 32);
        char* buf = sm + (ch & 1) * BUFB;

#pragma unroll
        for (int ks = 0; ks < 2; ++ks) {
            const int kk = ks * 16;
            uint32_t ah[2][4], al[2][4];
#pragma unroll
            for (int mf = 0; mf < 2; ++mf) {
                const int row = m0 + mf * 16 + (lane >> 2);
                const int base = row * 80 + kk * 2 + (lane & 3) * 4;
                const char* A = buf + OFF_AHI;
                ah[mf][0] = *reinterpret_cast<const uint32_t*>(A + base);
                ah[mf][1] = *reinterpret_cast<const uint32_t*>(A + base + 640);
                ah[mf][2] = *reinterpret_cast<const uint32_t*>(A + base + 16);
                ah[mf][3] = *reinterpret_cast<const uint32_t*>(A + base + 656);
                const char* B = buf + OFF_ALO;
                al[mf][0] = *reinterpret_cast<const uint32_t*>(B + base);
                al[mf][1] = *reinterpret_cast<const uint32_t*>(B + base + 640);
                al[mf][2] = *reinterpret_cast<const uint32_t*>(B + base + 16);
                al[mf][3] = *reinterpret_cast<const uint32_t*>(B + base + 656);
            }
#pragma unroll
            for (int half = 0; half < 2; ++half) {
                uint32_t bh[3][2], bl[3][2];
#pragma unroll
                for (int i = 0; i < 3; ++i) {
                    const int nf = half * 3 + i;
                    const int rowb = n0 + nf * 8 + (lane >> 2);
                    const int bb = rowb * 80 + kk * 2 + (lane & 3) * 4;
                    bh[i][0] = *reinterpret_cast<const uint32_t*>(buf + OFF_BHI + bb);
                    bh[i][1] = *reinterpret_cast<const uint32_t*>(buf + OFF_BHI + bb + 16);
                    bl[i][0] = *reinterpret_cast<const uint32_t*>(buf + OFF_BLO + bb);
                    bl[i][1] = *reinterpret_cast<const uint32_t*>(buf + OFF_BLO + bb + 16);
                }
#pragma unroll
                for (int mf = 0; mf < 2; ++mf)
#pragma unroll
                    for (int i = 0; i < 3; ++i) {
                        const int nf = half * 3 + i;
                        mma16816(acc[mf][nf], ah[mf], bh[i]);
                        mma16816(acc[mf][nf], ah[mf], bl[i]);
                        mma16816(acc[mf][nf], al[mf], bh[i]);
                    }
            }
        }

        if (ch + 1 < 32) {
            __syncthreads();
            sts_chunk(sm + ((ch + 1) & 1) * BUFB);
            __syncthreads();
        }
    }

    // ---- epilogue ----
#pragma unroll
    for (int mf = 0; mf < 2; ++mf) {
        const int rg = row0 + m0 + mf * 16 + (lane >> 2);
#pragma unroll
        for (int nf = 0; nf < 6; ++nf) {
            const int col = n0 + nf * 8 + (lane & 3) * 2;
            const int mat = col >> 6, h = col & 63;
            const float* bias = (mat == 0) ? bq : (mat == 1) ? bk : bv;
            const float b0 = bias[h], b1 = bias[h + 1];
            const float v00 = acc[mf][nf][0] + b0;
            const float v01 = acc[mf][nf][1] + b1;
            const float v10 = acc[mf][nf][2] + b0;
            const float v11 = acc[mf][nf][3] + b1;
            if (mat == 2) {
                float2 a = {v00, v01}, bvv = {v10, v11};
                *reinterpret_cast<float2*>(g_V + (size_t)rg * kH + h) = a;
                *reinterpret_cast<float2*>(g_V + (size_t)(rg + 8) * kH + h) = bvv;
            } else {
                const float scl = (mat == 0) ? 0.125f : 1.0f;  // fold softmax scale into Q
                __nv_bfloat16* Ah = (mat == 0) ? g_Qh : g_Kh;
                __nv_bfloat16* Al = (mat == 0) ? g_Ql : g_Kl;
                *reinterpret_cast<uint32_t*>(Ah + (size_t)rg * kH + h) =
                    pack_bf16x2(v00 * scl, v01 * scl);
                *reinterpret_cast<uint32_t*>(Al + (size_t)rg * kH + h) =
                    pack_bf16x2_lo(v00 * scl, v01 * scl);
                *reinterpret_cast<uint32_t*>(Ah + (size_t)(rg + 8) * kH + h) =
                    pack_bf16x2(v10 * scl, v11 * scl);
                *reinterpret_cast<uint32_t*>(Al + (size_t)(rg + 8) * kH + h) =
                    pack_bf16x2_lo(v10 * scl, v11 * scl);
            }
        }
    }
}

// ---------------------------------------------------------------------------
// V transpose + bf16 split: g_V [b][t][h] fp32 -> g_VTh/g_VTl [b][h][t] bf16
// ---------------------------------------------------------------------------
__global__ __launch_bounds__(256)
void vtrans_kernel() {
    __shared__ float tile[64][65];
    const int blk = blockIdx.x;            // kB * 32
    const int b = blk >> 5, t0 = (blk & 31) * 64;
    const int tid = threadIdx.x;
    const float* src = g_V + ((size_t)b * kT + t0) * kH;
#pragma unroll
    for (int i = 0; i < 16; ++i) {
        const int idx = tid + i * 256;
        tile[idx >> 6][idx & 63] = src[idx];
    }
    __syncthreads();
#pragma unroll
    for (int i = 0; i < 8; ++i) {
        const int idx = tid + i * 256;     // 2048 bf16x2 pairs
        const int h = idx >> 5, tp = (idx & 31) * 2;
        const float v0 = tile[tp][h], v1 = tile[tp + 1][h];
        const size_t off = ((size_t)b * kH + h) * kT + t0 + tp;
        *reinterpret_cast<uint32_t*>(g_VTh + off) = pack_bf16x2(v0, v1);
        *reinterpret_cast<uint32_t*>(g_VTl + off) = pack_bf16x2_lo(v0, v1);
    }
}

// ---------------------------------------------------------------------------
// Causal flash attention on HMMA, 3-term bf16 split, cp.async staging.
// CTA = (batch, 64-row q-tile), 128 threads = 4 warps, warp tile m16 x n64.
// K/V tiles double-buffered; staging = pure 16B async copies (pre-converted).
// ---------------------------------------------------------------------------
__global__ __launch_bounds__(128, 2)
void attn_mma_kernel(float* __restrict__ out) {
    extern __shared__ __align__(16) char sma[];
    char* Qh = sma + A_QH;
    char* Ql = sma + A_QL;

    const int tid  = threadIdx.x;
    const int lane = tid & 31;
    const int w    = tid >> 5;
    const int b    = blockIdx.x & 15;
    const int qt   = (kQT - 1) - (blockIdx.x >> 4);   // heaviest first
    const int q0   = qt * 64;
    const int m0w  = w * 16;
    const int r1   = lane >> 2;
    const int kq   = lane & 3;

    // ---- load Q tile once (pre-converted, pre-scaled bf16 hi/lo) ----
    {
        const char* qh = (const char*)(g_Qh + ((size_t)b * kT + q0) * kH);
        const char* ql = (const char*)(g_Ql + ((size_t)b * kT + q0) * kH);
#pragma unroll
        for (int i = 0; i < 4; ++i) {
            const int idx = tid + i * 128;         // 512 x 16B
            const int r = idx >> 3, c = (idx & 7) * 16;
            *reinterpret_cast<uint4*>(Qh + r * APAD + c) =
                *reinterpret_cast<const uint4*>(qh + idx * 16);
            *reinterpret_cast<uint4*>(Ql + r * APAD + c) =
                *reinterpret_cast<const uint4*>(ql + idx * 16);
        }
    }

    // ---- async stage of K/V tile jt into buffer ----
    auto stage = [&](int jt, char* buf) {
        const int j0 = jt * 64;
        const char* kh = (const char*)(g_Kh + ((size_t)b * kT + j0) * kH);
        const char* kl = (const char*)(g_Kl + ((size_t)b * kT + j0) * kH);
#pragma unroll
        for (int i = 0; i < 4; ++i) {
            const int idx = tid + i * 128;
            const int r = idx >> 3, c = (idx & 7) * 16;
            CP_ASYNC16(smem_addr(buf + BK_KH + r * APAD + c), kh + idx * 16);
            CP_ASYNC16(smem_addr(buf + BK_KL + r * APAD + c), kl + idx * 16);
        }
        const char* vh = (const char*)(g_VTh + (size_t)b * kH * kT + j0);
        const char* vl = (const char*)(g_VTl + (size_t)b * kH * kT + j0);
#pragma unroll
        for (int i = 0; i < 4; ++i) {
            const int idx = tid + i * 128;
            const int r = idx >> 3, c = (idx & 7) * 16;  // r = h row, c = t-chunk
            CP_ASYNC16(smem_addr(buf + BK_VH + r * APAD + c),
                       vh + (size_t)r * kT * 2 + c);
            CP_ASYNC16(smem_addr(buf + BK_VL + r * APAD + c),
                       vl + (size_t)r * kT * 2 + c);
        }
    };

    float o[8][4];
#pragma unroll
    for (int nf = 0; nf < 8; ++nf)
#pragma unroll
        for (int c = 0; c < 4; ++c) o[nf][c] = 0.f;
    float mrow[2] = {-1e30f, -1e30f};
    float lrow[2] = {0.f, 0.f};

    stage(0, sma + A_BUF);
    CP_COMMIT();

    for (int jt = 0; jt <= qt; ++jt) {
        // issue next tile's copies into the other buffer (its readers finished
        // at the end-of-iteration barrier of jt-1)
        if (jt + 1 <= qt) stage(jt + 1, sma + A_BUF + ((jt + 1) & 1) * ABUFSZ);
        CP_COMMIT();
        CP_WAIT1();          // tile jt's group complete
        __syncthreads();

        char* buf = sma + A_BUF + (jt & 1) * ABUFSZ;
        char* Kh = buf + BK_KH;
        char* Kl = buf + BK_KL;
        char* Vh = buf + BK_VH;
        char* Vl = buf + BK_VL;

        // ---- S = Q K^T (Q pre-scaled; 3-term split) ----
        float s[8][4];
#pragma unroll
        for (int nf = 0; nf < 8; ++nf)
#pragma unroll
            for (int c = 0; c < 4; ++c) s[nf][c] = 0.f;

#pragma unroll
        for (int ks = 0; ks < 4; ++ks) {
            const int abase = (m0w + r1) * APAD + ks * 32 + kq * 4;
            uint32_t ah[4], al[4];
            ah[0] = *reinterpret_cast<const uint32_t*>(Qh + abase);
            ah[1] = *reinterpret_cast<const uint32_t*>(Qh + abase + 8 * APAD);
            ah[2] = *reinterpret_cast<const uint32_t*>(Qh + abase + 16);
            ah[3] = *reinterpret_cast<const uint32_t*>(Qh + abase + 8 * APAD + 16);
            al[0] = *reinterpret_cast<const uint32_t*>(Ql + abase);
            al[1] = *reinterpret_cast<const uint32_t*>(Ql + abase + 8 * APAD);
            al[2] = *reinterpret_cast<const uint32_t*>(Ql + abase + 16);
            al[3] = *reinterpret_cast<const uint32_t*>(Ql + abase + 8 * APAD + 16);
#pragma unroll
            for (int nf = 0; nf < 8; ++nf) {
                const int bbase = (nf * 8 + r1) * APAD + ks * 32 + kq * 4;
                uint32_t bh[2], bl[2];
                bh[0] = *reinterpret_cast<const uint32_t*>(Kh + bbase);
                bh[1] = *reinterpret_cast<const uint32_t*>(Kh + bbase + 16);
                bl[0] = *reinterpret_cast<const uint32_t*>(Kl + bbase);
                bl[1] = *reinterpret_cast<const uint32_t*>(Kl + bbase + 16);
                mma16816(s[nf], ah, bh);
                mma16816(s[nf], ah, bl);
                mma16816(s[nf], al, bh);
            }
        }

        // ---- causal mask (diagonal tile only) + online softmax ----
        float mx1 = -1e30f, mx2 = -1e30f;
        if (jt == qt) {
            const int qg1 = q0 + m0w + r1;
            const int qg2 = qg1 + 8;
#pragma unroll
            for (int nf = 0; nf < 8; ++nf) {
                const int kg0 = jt * 64 + nf * 8 + kq * 2;
                s[nf][0] = (kg0     <= qg1) ? s[nf][0] : -1e30f;
                s[nf][1] = (kg0 + 1 <= qg1) ? s[nf][1] : -1e30f;
                s[nf][2] = (kg0     <= qg2) ? s[nf][2] : -1e30f;
                s[nf][3] = (kg0 + 1 <= qg2) ? s[nf][3] : -1e30f;
            }
        }
#pragma unroll
        for (int nf = 0; nf < 8; ++nf) {
            mx1 = fmaxf(mx1, fmaxf(s[nf][0], s[nf][1]));
            mx2 = fmaxf(mx2, fmaxf(s[nf][2], s[nf][3]));
        }
        mx1 = fmaxf(mx1, __shfl_xor_sync(0xffffffffu, mx1, 1));
        mx1 = fmaxf(mx1, __shfl_xor_sync(0xffffffffu, mx1, 2));
        mx2 = fmaxf(mx2, __shfl_xor_sync(0xffffffffu, mx2, 1));
        mx2 = fmaxf(mx2, __shfl_xor_sync(0xffffffffu, mx2, 2));

        const float mn1 = fmaxf(mrow[0], mx1);
        const float mn2 = fmaxf(mrow[1], mx2);
        const float a1 = __expf(mrow[0] - mn1);
        const float a2 = __expf(mrow[1] - mn2);
        mrow[0] = mn1; mrow[1] = mn2;

        float rs1 = 0.f, rs2 = 0.f;
#pragma unroll
        for (int nf = 0; nf < 8; ++nf) {
            s[nf][0] = __expf(s[nf][0] - mn1);
            s[nf][1] = __expf(s[nf][1] - mn1);
            s[nf][2] = __expf(s[nf][2] - mn2);
            s[nf][3] = __expf(s[nf][3] - mn2);
            rs1 += s[nf][0] + s[nf][1];
            rs2 += s[nf][2] + s[nf][3];
        }
        rs1 += __shfl_xor_sync(0xffffffffu, rs1, 1);
        rs1 += __shfl_xor_sync(0xffffffffu, rs1, 2);
        rs2 += __shfl_xor_sync(0xffffffffu, rs2, 1);
        rs2 += __shfl_xor_sync(0xffffffffu, rs2, 2);
        lrow[0] = lrow[0] * a1 + rs1;
        lrow[1] = lrow[1] * a2 + rs2;
#pragma unroll
        for (int nf = 0; nf < 8; ++nf) {
            o[nf][0] *= a1; o[nf][1] *= a1;
            o[nf][2] *= a2; o[nf][3] *= a2;
        }

        // ---- O += P V (P packed straight from accumulator frags) ----
#pragma unroll
        for (int ks = 0; ks < 4; ++ks) {
            uint32_t pa_h[4], pa_l[4];
            pa_h[0] = pack_bf16x2(s[2 * ks][0], s[2 * ks][1]);
            pa_h[1] = pack_bf16x2(s[2 * ks][2], s[2 * ks][3]);
            pa_h[2] = pack_bf16x2(s[2 * ks + 1][0], s[2 * ks + 1][1]);
            pa_h[3] = pack_bf16x2(s[2 * ks + 1][2], s[2 * ks + 1][3]);
            pa_l[0] = pack_bf16x2_lo(s[2 * ks][0], s[2 * ks][1]);
            pa_l[1] = pack_bf16x2_lo(s[2 * ks][2], s[2 * ks][3]);
            pa_l[2] = pack_bf16x2_lo(s[2 * ks + 1][0], s[2 * ks + 1][1]);
            pa_l[3] = pack_bf16x2_lo(s[2 * ks + 1][2], s[2 * ks + 1][3]);
#pragma unroll
            for (int nf = 0; nf < 8; ++nf) {
                const int bbase = (nf * 8 + r1) * APAD + ks * 32 + kq * 4;
                uint32_t vh2[2], vl2[2];
                vh2[0] = *reinterpret_cast<const uint32_t*>(Vh + bbase);
                vh2[1] = *reinterpret_cast<const uint32_t*>(Vh + bbase + 16);
                vl2[0] = *reinterpret_cast<const uint32_t*>(Vl + bbase);
                vl2[1] = *reinterpret_cast<const uint32_t*>(Vl + bbase + 16);
                mma16816(o[nf], pa_h, vh2);
                mma16816(o[nf], pa_h, vl2);
                mma16816(o[nf], pa_l, vh2);
            }
        }
        __syncthreads();   // readers of this buffer done before it is re-staged
    }

    // ---- epilogue: normalize + store ----
    const float inv1 = 1.0f / lrow[0];
    const float inv2 = 1.0f / lrow[1];
    float* og = out + ((size_t)b * kT + q0 + m0w) * kH;
#pragma unroll
    for (int nf = 0; nf < 8; ++nf) {
        const int col = nf * 8 + kq * 2;
        float2 v0, v1;
        v0.x = o[nf][0] * inv1; v0.y = o[nf][1] * inv1;
        v1.x = o[nf][2] * inv2; v1.y = o[nf][3] * inv2;
        *reinterpret_cast<float2*>(&og[r1 * kH + col]) = v0;
        *reinterpret_cast<float2*>(&og[(r1 + 8) * kH + col]) = v1;
    }
}

// ---------------------------------------------------------------------------
extern "C" void kernel_launch(void* const* d_in, const int* in_sizes, int n_in,
                              void* d_out, int out_size) {
    (void)in_sizes; (void)n_in; (void)out_size;
    const float* x  = (const float*)d_in[0];
    const float* Wq = (const float*)d_in[1];
    const float* bq = (const float*)d_in[2];
    const float* Wk = (const float*)d_in[3];
    const float* bk = (const float*)d_in[4];
    const float* Wv = (const float*)d_in[5];
    const float* bv = (const float*)d_in[6];
    float* out = (float*)d_out;

    wprep_kernel<<<(192 * 1024) / 256, 256>>>(Wq, Wk, Wv);

    cudaFuncSetAttribute(qkv_mma_kernel, cudaFuncAttributeMaxDynamicSharedMemorySize,
                         QKV_SMEM);
    qkv_mma_kernel<<<kRows / 128, 512, QKV_SMEM>>>(x, bq, bk, bv);

    vtrans_kernel<<<kB * 32, 256>>>();

    cudaFuncSetAttribute(attn_mma_kernel, cudaFuncAttributeMaxDynamicSharedMemorySize,
                         ATTN_SMEM);
    attn_mma_kernel<<<kB * kQT, 128, ATTN_SMEM>>>(out);
}